// round 13
// baseline (speedup 1.0000x reference)
#include <cuda_runtime.h>
#include <cstdint>

#define N_NODES 50000
#define N_EDGES 800000
#define D 128
#define BN_EPS 1e-5f
#define TOTAL4 (N_NODES * D / 4)

// ---------------- scratch (no allocations allowed) ----------------
__device__ double g_sum[D];
__device__ double g_sumsq[D];
__device__ float  g_scale[D];
__device__ float  g_bias[D];
__device__ unsigned g_done;
__device__ unsigned g_ready;

// ---------------- K1: init out = (1+eps)*h*norm^2, zero flags (2 float4/thread) ----------------
__global__ void __launch_bounds__(256) k_init(
    const float* __restrict__ h, const float* __restrict__ norm,
    const float* __restrict__ eps_p, float* __restrict__ out)
{
    int i = blockIdx.x * blockDim.x + threadIdx.x;
    if (i < D) { g_sum[i] = 0.0; g_sumsq[i] = 0.0; }
    if (i == 0) { g_done = 0; g_ready = 0; }

    int i0 = 2 * i;
    if (i0 >= TOTAL4) return;
    float epsv = 1.0f + eps_p[0];

    int r0 = i0 >> 5;
    int r1 = (i0 + 1) >> 5;
    float n0 = __ldg(norm + r0);
    float n1 = __ldg(norm + r1);
    float s0 = epsv * n0 * n0;
    float s1 = epsv * n1 * n1;
    float4 a = ((const float4*)h)[i0];
    float4 b = ((const float4*)h)[i0 + 1];
    ((float4*)out)[i0]     = make_float4(a.x * s0, a.y * s0, a.z * s0, a.w * s0);
    ((float4*)out)[i0 + 1] = make_float4(b.x * s1, b.y * s1, b.z * s1, b.w * s1);
}

// ---------------- K2: edge scatter (2 edges per warp — R9 proven) ----------------
__global__ void __launch_bounds__(256) k_edges(
    const float* __restrict__ h, const float* __restrict__ norm,
    const int* __restrict__ src, const int* __restrict__ dst,
    float* __restrict__ out)
{
    long long t = (long long)blockIdx.x * blockDim.x + threadIdx.x;
    int w    = (int)(t >> 5);            // warp id = edge pair id
    int lane = (int)(t & 31);
    if (2 * w >= N_EDGES) return;

    int2 s2 = __ldg((const int2*)src + w);   // warp-uniform
    int2 d2 = __ldg((const int2*)dst + w);   // warp-uniform
    float w0 = __ldg(norm + s2.x) * __ldg(norm + d2.x);
    float w1 = __ldg(norm + s2.y) * __ldg(norm + d2.y);

    float4 a = __ldg((const float4*)(h + (size_t)s2.x * D) + lane);
    float4 b = __ldg((const float4*)(h + (size_t)s2.y * D) + lane);

    float4 va = make_float4(a.x * w0, a.y * w0, a.z * w0, a.w * w0);
    float4 vb = make_float4(b.x * w1, b.y * w1, b.z * w1, b.w * w1);

    float* p0 = out + (size_t)d2.x * D + lane * 4;
    float* p1 = out + (size_t)d2.y * D + lane * 4;
    asm volatile("red.global.add.v4.f32 [%0], {%1,%2,%3,%4};"
                 :: "l"(p0), "f"(va.x), "f"(va.y), "f"(va.z), "f"(va.w) : "memory");
    asm volatile("red.global.add.v4.f32 [%0], {%1,%2,%3,%4};"
                 :: "l"(p1), "f"(vb.x), "f"(vb.y), "f"(vb.z), "f"(vb.w) : "memory");
}

// ---------------- K3: fused stats + grid sync + BN apply + ReLU ----------------
// Persistent at FULL occupancy: 1184 blocks = 148 SMs x 8, co-resident by
// __launch_bounds__(256, 8) (regs <=32, smem ~3.5KB << 28.5KB/block budget).
#define FUSE_BLOCKS 1184
__global__ void __launch_bounds__(256, 8) k_stats_bn(
    const float* __restrict__ gamma, const float* __restrict__ beta,
    float* __restrict__ out)
{
    int c    = threadIdx.x & 127;        // channel
    int half = threadIdx.x >> 7;         // 0/1: two rows in flight per block

    // ---- phase A: stats partials (row-strided, balanced) ----
    float lsum = 0.f, lsq = 0.f;
    for (int row = blockIdx.x * 2 + half; row < N_NODES; row += FUSE_BLOCKS * 2) {
        float v = __ldg(out + (size_t)row * D + c);
        lsum += v;
        lsq  = fmaf(v, v, lsq);
    }
    __shared__ float s_s[2][D];
    __shared__ float s_q[2][D];
    s_s[half][c] = lsum;
    s_q[half][c] = lsq;
    __syncthreads();
    if (threadIdx.x < D) {
        atomicAdd(&g_sum[threadIdx.x],
                  (double)(s_s[0][threadIdx.x] + s_s[1][threadIdx.x]));
        atomicAdd(&g_sumsq[threadIdx.x],
                  (double)(s_q[0][threadIdx.x] + s_q[1][threadIdx.x]));
    }

    // ---- last block finalizes scale/bias ----
    __threadfence();
    __syncthreads();
    __shared__ int s_last;
    if (threadIdx.x == 0)
        s_last = (atomicAdd(&g_done, 1u) == (unsigned)(FUSE_BLOCKS - 1));
    __syncthreads();
    if (s_last) {
        if (threadIdx.x < D) {
            int ch = threadIdx.x;
            double su  = __ldcg(&g_sum[ch]);
            double ssq = __ldcg(&g_sumsq[ch]);
            double mu  = su / (double)N_NODES;
            double var = ssq / (double)N_NODES - mu * mu;
            double rstd = 1.0 / sqrt(var + (double)BN_EPS);
            float sc = gamma[ch] * (float)rstd;
            g_scale[ch] = sc;
            g_bias[ch]  = beta[ch] - (float)mu * sc;
        }
        __syncthreads();
        __threadfence();
        if (threadIdx.x == 0) atomicExch(&g_ready, 1u);
    }

    // ---- grid-wide wait (all 1184 blocks co-resident) ----
    if (threadIdx.x == 0) {
        volatile unsigned* vr = &g_ready;
        while (*vr == 0u) __nanosleep(64);
    }
    __syncthreads();

    // ---- phase B: BN apply + ReLU (full occupancy grid-stride) ----
    __shared__ float4 s_sc4[D / 4];
    __shared__ float4 s_bi4[D / 4];
    if (threadIdx.x < D) {
        ((float*)s_sc4)[threadIdx.x] = __ldcg(&g_scale[threadIdx.x]);
        ((float*)s_bi4)[threadIdx.x] = __ldcg(&g_bias[threadIdx.x]);
    }
    __syncthreads();

    for (int i4 = blockIdx.x * 256 + threadIdx.x; i4 < TOTAL4;
         i4 += FUSE_BLOCKS * 256) {
        int c4 = i4 & (D / 4 - 1);
        float4 sc = s_sc4[c4];
        float4 bi = s_bi4[c4];
        float4 x = ((float4*)out)[i4];
        x.x = fmaxf(fmaf(x.x, sc.x, bi.x), 0.f);
        x.y = fmaxf(fmaf(x.y, sc.y, bi.y), 0.f);
        x.z = fmaxf(fmaf(x.z, sc.z, bi.z), 0.f);
        x.w = fmaxf(fmaf(x.w, sc.w, bi.w), 0.f);
        ((float4*)out)[i4] = x;
    }
}

// ---------------- launch ----------------
extern "C" void kernel_launch(void* const* d_in, const int* in_sizes, int n_in,
                              void* d_out, int out_size)
{
    const float* h     = (const float*)d_in[0];
    const float* norm  = (const float*)d_in[1];
    const float* eps   = (const float*)d_in[2];
    const float* gamma = (const float*)d_in[3];
    const float* beta  = (const float*)d_in[4];
    const int*   src   = (const int*)d_in[5];
    const int*   dst   = (const int*)d_in[6];
    float* out = (float*)d_out;

    (void)in_sizes; (void)n_in; (void)out_size;

    const int ipairs = (TOTAL4 + 1) / 2;
    k_init<<<(ipairs + 255) / 256, 256>>>(h, norm, eps, out);

    const long long ethreads = (long long)(N_EDGES / 2) * 32;
    k_edges<<<(unsigned)((ethreads + 255) / 256), 256>>>(h, norm, src, dst, out);

    k_stats_bn<<<FUSE_BLOCKS, 256>>>(gamma, beta, out);
}